// round 1
// baseline (speedup 1.0000x reference)
#include <cuda_runtime.h>
#include <cstdint>

// Problem dims
#define RDIM 128
#define CDIM 384
#define EDIM 768
#define HDIM 12
#define DDIM 64
#define MDIM (RDIM * CDIM)   // 49152

// smem pitches (bank-conflict engineered)
#define QP 68     // Q/K/V tile pitch (floats): 8-row float4 reads land on distinct bank groups
#define SP 132    // score tile pitch (floats): float4-aligned, row scans <=4-way

// Scratch (allocation-free rule: __device__ globals)
__device__ float g_q[(size_t)MDIM * EDIM];
__device__ float g_k[(size_t)MDIM * EDIM];
__device__ float g_v[(size_t)MDIM * EDIM];
__device__ float g_ctx[(size_t)MDIM * EDIM];

// ---------------------------------------------------------------------------
// 128x128 tile SGEMM core: C_tile = A[bm:bm+128, :] * W[bn:bn+128, :]^T
// A: [M, 768] row-major, W: [768, 768] row-major (torch Linear weight).
// 256 threads, 8x8 per-thread accumulators, BK=8.
// ---------------------------------------------------------------------------
__device__ __forceinline__ void gemm128x128(
    const float* __restrict__ A, const float* __restrict__ W,
    int bm, int bn, float (&acc)[8][8])
{
    __shared__ float As[8][128];
    __shared__ float Bs[8][128];

    const int t = threadIdx.x;
    const int tx = t & 15;
    const int ty = t >> 4;
    const int lrow = t >> 1;          // 0..127
    const int lcol = (t & 1) << 2;    // 0 or 4

    const float* Ap = A + (size_t)(bm + lrow) * EDIM + lcol;
    const float* Wp = W + (size_t)(bn + lrow) * EDIM + lcol;

#pragma unroll
    for (int i = 0; i < 8; ++i)
#pragma unroll
        for (int j = 0; j < 8; ++j) acc[i][j] = 0.0f;

    for (int k0 = 0; k0 < EDIM; k0 += 8) {
        const float4 av = *(const float4*)(Ap + k0);
        const float4 wv = *(const float4*)(Wp + k0);
        __syncthreads();
        As[lcol + 0][lrow] = av.x;
        As[lcol + 1][lrow] = av.y;
        As[lcol + 2][lrow] = av.z;
        As[lcol + 3][lrow] = av.w;
        Bs[lcol + 0][lrow] = wv.x;
        Bs[lcol + 1][lrow] = wv.y;
        Bs[lcol + 2][lrow] = wv.z;
        Bs[lcol + 3][lrow] = wv.w;
        __syncthreads();
#pragma unroll
        for (int k = 0; k < 8; ++k) {
            float a[8], b[8];
            *(float4*)(a)     = *(const float4*)(&As[k][ty * 8]);
            *(float4*)(a + 4) = *(const float4*)(&As[k][ty * 8 + 4]);
            *(float4*)(b)     = *(const float4*)(&Bs[k][tx * 8]);
            *(float4*)(b + 4) = *(const float4*)(&Bs[k][tx * 8 + 4]);
#pragma unroll
            for (int i = 0; i < 8; ++i)
#pragma unroll
                for (int j = 0; j < 8; ++j)
                    acc[i][j] = fmaf(a[i], b[j], acc[i][j]);
        }
    }
}

// ---------------------------------------------------------------------------
// Fused Q/K/V projection. grid = (384, 18): y/6 selects q(scaled)/k/v.
// Output layout: [c][h][i][d]  (contiguous 128x64 tiles per (c,h) for attention)
// ---------------------------------------------------------------------------
__global__ __launch_bounds__(256)
void qkv_gemm(const float* __restrict__ x,
              const float* __restrict__ wq, const float* __restrict__ bq,
              const float* __restrict__ wk, const float* __restrict__ bk,
              const float* __restrict__ wv, const float* __restrict__ bv)
{
    const int bm  = blockIdx.x * 128;
    const int sel = blockIdx.y / 6;
    const int bn  = (blockIdx.y % 6) * 128;

    const float* W    = (sel == 0) ? wq : (sel == 1) ? wk : wv;
    const float* bias = (sel == 0) ? bq : (sel == 1) ? bk : bv;
    float* out        = (sel == 0) ? g_q : (sel == 1) ? g_k : g_v;
    const float scale = (sel == 0) ? 0.125f : 1.0f;  // D^-0.5 = 1/8

    float acc[8][8];
    gemm128x128(x, W, bm, bn, acc);

    const int tx = threadIdx.x & 15;
    const int ty = threadIdx.x >> 4;
#pragma unroll
    for (int i = 0; i < 8; ++i) {
        const int m   = bm + ty * 8 + i;
        const int row = m / CDIM;   // i (sequence row)
        const int col = m % CDIM;   // c (column)
#pragma unroll
        for (int j = 0; j < 8; ++j) {
            const int f = bn + tx * 8 + j;
            const int h = f >> 6;
            const int d = f & 63;
            const float v = (acc[i][j] + bias[f]) * scale;
            out[(((size_t)col * HDIM + h) * RDIM + row) * DDIM + d] = v;
        }
    }
}

// ---------------------------------------------------------------------------
// Output projection: out[m, f] = ctx[m, :] . wo[f, :] + bo[f]
// ---------------------------------------------------------------------------
__global__ __launch_bounds__(256)
void out_gemm(const float* __restrict__ wo, const float* __restrict__ bo,
              float* __restrict__ out)
{
    const int bm = blockIdx.x * 128;
    const int bn = blockIdx.y * 128;

    float acc[8][8];
    gemm128x128(g_ctx, wo, bm, bn, acc);

    const int tx = threadIdx.x & 15;
    const int ty = threadIdx.x >> 4;
#pragma unroll
    for (int i = 0; i < 8; ++i) {
        const int m = bm + ty * 8 + i;
#pragma unroll
        for (int j = 0; j < 8; ++j) {
            const int f = bn + tx * 8 + j;
            out[(size_t)m * EDIM + f] = acc[i][j] + bo[f];
        }
    }
}

// ---------------------------------------------------------------------------
// Attention per (c, h): S = Q K^T, mask, softmax -> probs out, ctx = P V.
// 256 threads; S tile via 16x16 thread grid, strided 8x8 per-thread tiles.
// ---------------------------------------------------------------------------
__global__ __launch_bounds__(256)
void attn_kernel(const unsigned char* __restrict__ mask,
                 float* __restrict__ probs)
{
    extern __shared__ float sm[];
    float* Qs = sm;                       // [128][QP]
    float* Ks = Qs + 128 * QP;            // [128][QP]
    float* Vs = Ks + 128 * QP;            // [128][QP]
    float* Ss = Vs + 128 * QP;            // [128][SP]
    float* Mk = Ss + 128 * SP;            // [128]

    const int c = blockIdx.x;
    const int h = blockIdx.y;
    const int t = threadIdx.x;
    const int tx = t & 15;
    const int ty = t >> 4;

    const size_t base = ((size_t)c * HDIM + h) * (RDIM * DDIM);
    const float* Qg = g_q + base;
    const float* Kg = g_k + base;
    const float* Vg = g_v + base;

    // Load Q/K/V tiles (contiguous 128x64 each), float4, no transpose needed.
#pragma unroll
    for (int it = 0; it < 8; ++it) {
        const int f4 = it * 256 + t;
        const int r  = f4 >> 4;
        const int d4 = (f4 & 15) << 2;
        const float4 q4 = *(const float4*)(Qg + (size_t)r * DDIM + d4);
        const float4 k4 = *(const float4*)(Kg + (size_t)r * DDIM + d4);
        const float4 v4 = *(const float4*)(Vg + (size_t)r * DDIM + d4);
        *(float4*)(&Qs[r * QP + d4]) = q4;
        *(float4*)(&Ks[r * QP + d4]) = k4;
        *(float4*)(&Vs[r * QP + d4]) = v4;
    }
    // mask flags for column c: mask shape (B=1, R, C); masks key index j.
    if (t < RDIM) Mk[t] = mask[(size_t)t * CDIM + c] ? 1.0f : 0.0f;
    __syncthreads();

    // ---- S = Q K^T (128x128), strided 8x8 per-thread tile ----
    {
        float acc[8][8];
#pragma unroll
        for (int i = 0; i < 8; ++i)
#pragma unroll
            for (int j = 0; j < 8; ++j) acc[i][j] = 0.0f;

        for (int d4 = 0; d4 < DDIM; d4 += 4) {
            float4 qf[8], kf[8];
#pragma unroll
            for (int u = 0; u < 8; ++u) {
                qf[u] = *(const float4*)(&Qs[(ty + 16 * u) * QP + d4]);
                kf[u] = *(const float4*)(&Ks[(tx + 16 * u) * QP + d4]);
            }
#pragma unroll
            for (int i = 0; i < 8; ++i)
#pragma unroll
                for (int j = 0; j < 8; ++j) {
                    acc[i][j] = fmaf(qf[i].x, kf[j].x, acc[i][j]);
                    acc[i][j] = fmaf(qf[i].y, kf[j].y, acc[i][j]);
                    acc[i][j] = fmaf(qf[i].z, kf[j].z, acc[i][j]);
                    acc[i][j] = fmaf(qf[i].w, kf[j].w, acc[i][j]);
                }
        }
#pragma unroll
        for (int i = 0; i < 8; ++i)
#pragma unroll
            for (int j = 0; j < 8; ++j)
                Ss[(ty + 16 * i) * SP + (tx + 16 * j)] = acc[i][j];
    }
    __syncthreads();

    // ---- masked softmax, one row per thread (t < 128) ----
    if (t < RDIM) {
        float* Srow = Ss + t * SP;
        float mx = -3.0e38f;
        for (int j = 0; j < RDIM; ++j) {
            float v = Srow[j];
            if (Mk[j] != 0.0f) v = -10000.0f;
            Srow[j] = v;
            mx = fmaxf(mx, v);
        }
        float s = 0.0f;
        for (int j = 0; j < RDIM; ++j) {
            const float e = __expf(Srow[j] - mx);
            Srow[j] = e;
            s += e;
        }
        const float inv = 1.0f / s;
        for (int j = 0; j < RDIM; ++j) Srow[j] *= inv;
    }
    __syncthreads();

    // ---- write attn_probs (H, C, 1, R, R) coalesced ----
    float* pb = probs + ((size_t)h * CDIM + c) * (RDIM * RDIM);
#pragma unroll
    for (int it = 0; it < 16; ++it) {
        const int f4 = it * 256 + t;
        const int i  = f4 >> 5;
        const int j4 = (f4 & 31) << 2;
        const float4 v = *(const float4*)(&Ss[i * SP + j4]);
        *(float4*)(pb + (size_t)i * RDIM + j4) = v;
    }

    // ---- ctx = P V (128x64), 8 rows x 4 cols per thread ----
    {
        float acc[8][4];
#pragma unroll
        for (int u = 0; u < 8; ++u)
#pragma unroll
            for (int q = 0; q < 4; ++q) acc[u][q] = 0.0f;

        for (int j = 0; j < RDIM; ++j) {
            const float4 v4 = *(const float4*)(&Vs[j * QP + (tx << 2)]);
#pragma unroll
            for (int u = 0; u < 8; ++u) {
                const float p = Ss[(ty + 16 * u) * SP + j];
                acc[u][0] = fmaf(p, v4.x, acc[u][0]);
                acc[u][1] = fmaf(p, v4.y, acc[u][1]);
                acc[u][2] = fmaf(p, v4.z, acc[u][2]);
                acc[u][3] = fmaf(p, v4.w, acc[u][3]);
            }
        }
#pragma unroll
        for (int u = 0; u < 8; ++u) {
            const int i = ty + 16 * u;
            float4 o;
            o.x = acc[u][0]; o.y = acc[u][1]; o.z = acc[u][2]; o.w = acc[u][3];
            *(float4*)(&g_ctx[((size_t)i * CDIM + c) * EDIM + h * DDIM + (tx << 2)]) = o;
        }
    }
}

// ---------------------------------------------------------------------------
extern "C" void kernel_launch(void* const* d_in, const int* in_sizes, int n_in,
                              void* d_out, int out_size)
{
    const float* x  = (const float*)d_in[0];
    // d_in[1] = distances (unused by the module)
    const unsigned char* mask = (const unsigned char*)d_in[2];
    const float* wq = (const float*)d_in[3];
    const float* bq = (const float*)d_in[4];
    const float* wk = (const float*)d_in[5];
    const float* bk = (const float*)d_in[6];
    const float* wv = (const float*)d_in[7];
    const float* bv = (const float*)d_in[8];
    const float* wo = (const float*)d_in[9];
    const float* bo = (const float*)d_in[10];

    float* out   = (float*)d_out;                    // (R, C, 1, E)
    float* probs = out + (size_t)MDIM * EDIM;        // (H, C, 1, R, R)

    const int attn_smem = (3 * 128 * QP + 128 * SP + 128) * (int)sizeof(float);
    cudaFuncSetAttribute(attn_kernel, cudaFuncAttributeMaxDynamicSharedMemorySize,
                         attn_smem);

    qkv_gemm<<<dim3(MDIM / 128, 18), 256>>>(x, wq, bq, wk, bk, wv, bv);
    attn_kernel<<<dim3(CDIM, HDIM), 256, attn_smem>>>(mask, probs);
    out_gemm<<<dim3(MDIM / 128, 6), 256>>>(wo, bo, out);
}

// round 3
// speedup vs baseline: 2.3869x; 2.3869x over previous
#include <cuda_runtime.h>
#include <cuda_bf16.h>
#include <cstdint>

#define RDIM 128
#define CDIM 384
#define EDIM 768
#define HDIM 12
#define DDIM 64
#define MDIM (RDIM * CDIM)   // 49152

// attention smem pitches
#define QP 68
#define SP 132

// GEMM tiling
#define BK 32
#define PITCH 40            // bf16 elements per smem row (80B, conflict-free ldmatrix)
#define MTX_BYTES (128 * PITCH * 2)        // 10240 per matrix tile
#define BUF_BYTES (4 * MTX_BYTES)          // Ah, Al, Bh, Bl

// ---------------- device scratch (allocation-free rule) ----------------
__device__ float g_q[(size_t)MDIM * EDIM];
__device__ float g_k[(size_t)MDIM * EDIM];
__device__ float g_v[(size_t)MDIM * EDIM];
__device__ __nv_bfloat16 g_ah[(size_t)MDIM * EDIM];     // A hi (x, then ctx)
__device__ __nv_bfloat16 g_al[(size_t)MDIM * EDIM];     // A lo
__device__ __nv_bfloat16 g_wh[(size_t)4 * EDIM * EDIM]; // packed wq|wk|wv|wo hi
__device__ __nv_bfloat16 g_wl[(size_t)4 * EDIM * EDIM]; // lo
__device__ float g_bias[4 * EDIM];

// ---------------- helpers ----------------
__device__ __forceinline__ uint32_t smem_to_u32(const void* p) {
    uint32_t a;
    asm("{ .reg .u64 t; cvta.to.shared.u64 t, %1; cvt.u32.u64 %0, t; }"
        : "=r"(a) : "l"(p));
    return a;
}

__device__ __forceinline__ void cp16(uint32_t dst, const void* src) {
    asm volatile("cp.async.cg.shared.global [%0], [%1], 16;"
                 :: "r"(dst), "l"(src) : "memory");
}
__device__ __forceinline__ void cp_commit() {
    asm volatile("cp.async.commit_group;" ::: "memory");
}
__device__ __forceinline__ void cp_wait0() {
    asm volatile("cp.async.wait_group 0;" ::: "memory");
}

__device__ __forceinline__ void ldmx4(uint32_t (&r)[4], uint32_t addr) {
    asm volatile("ldmatrix.sync.aligned.m8n8.x4.shared.b16 {%0,%1,%2,%3}, [%4];"
                 : "=r"(r[0]), "=r"(r[1]), "=r"(r[2]), "=r"(r[3]) : "r"(addr));
}

__device__ __forceinline__ void mma16816(float (&d)[4], const uint32_t (&a)[4],
                                         uint32_t b0, uint32_t b1) {
    asm volatile(
        "mma.sync.aligned.m16n8k16.row.col.f32.bf16.bf16.f32 "
        "{%0,%1,%2,%3}, {%4,%5,%6,%7}, {%8,%9}, {%0,%1,%2,%3};"
        : "+f"(d[0]), "+f"(d[1]), "+f"(d[2]), "+f"(d[3])
        : "r"(a[0]), "r"(a[1]), "r"(a[2]), "r"(a[3]), "r"(b0), "r"(b1));
}

__device__ __forceinline__ void split2(float f, __nv_bfloat16& h, __nv_bfloat16& l) {
    h = __float2bfloat16(f);
    l = __float2bfloat16(f - __bfloat162float(h));
}

// ---------------- conversion kernels ----------------
__global__ void conv_x(const float* __restrict__ src, int n4) {
    int i = blockIdx.x * blockDim.x + threadIdx.x;
    if (i >= n4) return;
    float4 v = ((const float4*)src)[i];
    __nv_bfloat16 h0, h1, h2, h3, l0, l1, l2, l3;
    split2(v.x, h0, l0); split2(v.y, h1, l1); split2(v.z, h2, l2); split2(v.w, h3, l3);
    size_t o = (size_t)i * 4;
    *(__nv_bfloat162*)(g_ah + o)     = __nv_bfloat162(h0, h1);
    *(__nv_bfloat162*)(g_ah + o + 2) = __nv_bfloat162(h2, h3);
    *(__nv_bfloat162*)(g_al + o)     = __nv_bfloat162(l0, l1);
    *(__nv_bfloat162*)(g_al + o + 2) = __nv_bfloat162(l2, l3);
}

__global__ void conv_w(const float* __restrict__ wq, const float* __restrict__ wk,
                       const float* __restrict__ wv, const float* __restrict__ wo,
                       const float* __restrict__ bq, const float* __restrict__ bk,
                       const float* __restrict__ bv, const float* __restrict__ bo)
{
    const size_t WSZ = (size_t)EDIM * EDIM;
    size_t i = (size_t)blockIdx.x * blockDim.x + threadIdx.x;
    int sel = (int)(i / WSZ);
    size_t off = i - (size_t)sel * WSZ;
    const float* w = (sel == 0) ? wq : (sel == 1) ? wk : (sel == 2) ? wv : wo;
    __nv_bfloat16 h, l;
    split2(w[off], h, l);
    g_wh[i] = h; g_wl[i] = l;
    if (i < 4 * EDIM) {
        int s = (int)(i / EDIM), r = (int)(i % EDIM);
        const float* b = (s == 0) ? bq : (s == 1) ? bk : (s == 2) ? bv : bo;
        g_bias[i] = b[r];
    }
}

// ---------------- split-bf16 HMMA GEMM ----------------
// C[128x128] tile = A[128,768] * Wpacked[nb..nb+128, 768]^T (+bias)
// mode 0: scatter to g_q/g_k/g_v ([c][h][i][d], q scaled); mode 1: out[m][f]
__global__ __launch_bounds__(512)
void gemm_tc(int n_off, int mode, float* __restrict__ outp)
{
    extern __shared__ char smdyn[];
    const uint32_t smb = smem_to_u32(smdyn);
    const int t = threadIdx.x;
    const int wid = t >> 5, lane = t & 31;
    const int wm = wid & 3, wn = wid >> 2;          // 4x4 warp grid
    const int bm = blockIdx.x * 128;
    const int nb = n_off + blockIdx.y * 128;

    const __nv_bfloat16* Agh = g_ah + (size_t)bm * EDIM;
    const __nv_bfloat16* Agl = g_al + (size_t)bm * EDIM;
    const __nv_bfloat16* Bgh = g_wh + (size_t)nb * EDIM;
    const __nv_bfloat16* Bgl = g_wl + (size_t)nb * EDIM;

    // per-thread cp.async geometry: 512 threads, 512 16B-chunks per matrix
    const int cr  = t >> 2;          // row 0..127
    const int cc  = (t & 3) * 16;    // byte col 0/16/32/48 within 64B row payload
    const uint32_t cp_dst0 = smb + (uint32_t)(cr * (PITCH * 2) + cc);
    const int cp_src_off = cr * EDIM + (cc >> 1);

    float acc[2][4][4];
#pragma unroll
    for (int mi = 0; mi < 2; ++mi)
#pragma unroll
        for (int ni = 0; ni < 4; ++ni)
#pragma unroll
            for (int e = 0; e < 4; ++e) acc[mi][ni][e] = 0.0f;

    // ldmatrix lane addressing
    const int lrow8 = (lane & 7) + ((lane >> 3) & 1) * 8;  // row within 16
    const int lkoff = (lane >> 4) * 8;                      // k-half

    // prefetch chunk 0
    {
        cp16(cp_dst0,                 Agh + cp_src_off);
        cp16(cp_dst0 + MTX_BYTES,     Agl + cp_src_off);
        cp16(cp_dst0 + 2 * MTX_BYTES, Bgh + cp_src_off);
        cp16(cp_dst0 + 3 * MTX_BYTES, Bgl + cp_src_off);
        cp_commit();
    }

    const int NC = EDIM / BK;  // 24
#pragma unroll 1
    for (int ch = 0; ch < NC; ++ch) {
        cp_wait0();
        __syncthreads();
        if (ch + 1 < NC) {
            const uint32_t d = cp_dst0 + ((ch + 1) & 1) * BUF_BYTES;
            const int s = cp_src_off + (ch + 1) * BK;
            cp16(d,                 Agh + s);
            cp16(d + MTX_BYTES,     Agl + s);
            cp16(d + 2 * MTX_BYTES, Bgh + s);
            cp16(d + 3 * MTX_BYTES, Bgl + s);
            cp_commit();
        }
        const uint32_t buf = smb + (ch & 1) * BUF_BYTES;
        const uint32_t aAh = buf + (uint32_t)((wm * 32 + lrow8) * (PITCH * 2));
        const uint32_t aB  = buf + 2 * MTX_BYTES +
                             (uint32_t)((wn * 32 + lrow8) * (PITCH * 2));
#pragma unroll
        for (int ks = 0; ks < 2; ++ks) {
            const uint32_t kbyte = (uint32_t)((ks * 16 + lkoff) * 2);
            uint32_t ah[2][4], al[2][4], bh[2][4], bl[2][4];
#pragma unroll
            for (int mi = 0; mi < 2; ++mi) {
                ldmx4(ah[mi], aAh + (uint32_t)(mi * 16 * PITCH * 2) + kbyte);
                ldmx4(al[mi], aAh + MTX_BYTES + (uint32_t)(mi * 16 * PITCH * 2) + kbyte);
            }
#pragma unroll
            for (int nbk = 0; nbk < 2; ++nbk) {
                ldmx4(bh[nbk], aB + (uint32_t)(nbk * 16 * PITCH * 2) + kbyte);
                ldmx4(bl[nbk], aB + MTX_BYTES + (uint32_t)(nbk * 16 * PITCH * 2) + kbyte);
            }
#pragma unroll
            for (int mi = 0; mi < 2; ++mi)
#pragma unroll
                for (int ni = 0; ni < 4; ++ni) {
                    const int nk = ni >> 1, lo = ni & 1;
                    mma16816(acc[mi][ni], ah[mi], bh[nk][lo], bh[nk][lo + 2]);
                    mma16816(acc[mi][ni], ah[mi], bl[nk][lo], bl[nk][lo + 2]);
                    mma16816(acc[mi][ni], al[mi], bh[nk][lo], bh[nk][lo + 2]);
                }
        }
    }

    // epilogue: each thread owns 2 rows x 2 cols per (mi, ni) frag
    const int r0 = bm + wm * 32 + (lane >> 2);
    const int cbase = nb + wn * 32 + (lane & 3) * 2;
#pragma unroll
    for (int mi = 0; mi < 2; ++mi) {
#pragma unroll
        for (int half = 0; half < 2; ++half) {
            const int m = r0 + mi * 16 + half * 8;
            const int i_ = m / CDIM, c_ = m % CDIM;
#pragma unroll
            for (int ni = 0; ni < 4; ++ni) {
                const int ng = cbase + ni * 8;
                float2 o;
                o.x = acc[mi][ni][half * 2 + 0] + g_bias[ng + 0];
                o.y = acc[mi][ni][half * 2 + 1] + g_bias[ng + 1];
                if (mode == 0) {
                    if (ng < EDIM) { o.x *= 0.125f; o.y *= 0.125f; }
                    const int sel = ng / EDIM, f = ng % EDIM, h = f >> 6, d = f & 63;
                    float* dst = (sel == 0) ? g_q : (sel == 1) ? g_k : g_v;
                    *(float2*)(dst + (((size_t)c_ * HDIM + h) * RDIM + i_) * DDIM + d) = o;
                } else {
                    *(float2*)(outp + (size_t)m * EDIM + (ng - 3 * EDIM)) = o;
                }
            }
        }
    }
}

// ---------------- attention ----------------
__global__ __launch_bounds__(256)
void attn_kernel(const unsigned char* __restrict__ mask,
                 float* __restrict__ probs)
{
    extern __shared__ float sm[];
    float* Qs = sm;
    float* Ks = Qs + 128 * QP;
    float* Vs = Ks + 128 * QP;
    float* Ss = Vs + 128 * QP;
    float* Mk = Ss + 128 * SP;

    const int c = blockIdx.x;
    const int h = blockIdx.y;
    const int t = threadIdx.x;
    const int tx = t & 15;
    const int ty = t >> 4;

    const size_t base = ((size_t)c * HDIM + h) * (RDIM * DDIM);
    const float* Qg = g_q + base;
    const float* Kg = g_k + base;
    const float* Vg = g_v + base;

#pragma unroll
    for (int it = 0; it < 8; ++it) {
        const int f4 = it * 256 + t;
        const int r  = f4 >> 4;
        const int d4 = (f4 & 15) << 2;
        *(float4*)(&Qs[r * QP + d4]) = *(const float4*)(Qg + (size_t)r * DDIM + d4);
        *(float4*)(&Ks[r * QP + d4]) = *(const float4*)(Kg + (size_t)r * DDIM + d4);
        *(float4*)(&Vs[r * QP + d4]) = *(const float4*)(Vg + (size_t)r * DDIM + d4);
    }
    if (t < RDIM) Mk[t] = mask[(size_t)t * CDIM + c] ? 1.0f : 0.0f;
    __syncthreads();

    {
        float acc[8][8];
#pragma unroll
        for (int i = 0; i < 8; ++i)
#pragma unroll
            for (int j = 0; j < 8; ++j) acc[i][j] = 0.0f;

        for (int d4 = 0; d4 < DDIM; d4 += 4) {
            float4 qf[8], kf[8];
#pragma unroll
            for (int u = 0; u < 8; ++u) {
                qf[u] = *(const float4*)(&Qs[(ty + 16 * u) * QP + d4]);
                kf[u] = *(const float4*)(&Ks[(tx + 16 * u) * QP + d4]);
            }
#pragma unroll
            for (int i = 0; i < 8; ++i)
#pragma unroll
                for (int j = 0; j < 8; ++j) {
                    acc[i][j] = fmaf(qf[i].x, kf[j].x, acc[i][j]);
                    acc[i][j] = fmaf(qf[i].y, kf[j].y, acc[i][j]);
                    acc[i][j] = fmaf(qf[i].z, kf[j].z, acc[i][j]);
                    acc[i][j] = fmaf(qf[i].w, kf[j].w, acc[i][j]);
                }
        }
#pragma unroll
        for (int i = 0; i < 8; ++i)
#pragma unroll
            for (int j = 0; j < 8; ++j)
                Ss[(ty + 16 * i) * SP + (tx + 16 * j)] = acc[i][j];
    }
    __syncthreads();

    if (t < RDIM) {
        float* Srow = Ss + t * SP;
        float mx = -3.0e38f;
        for (int j = 0; j < RDIM; ++j) {
            float v = Srow[j];
            if (Mk[j] != 0.0f) v = -10000.0f;
            Srow[j] = v;
            mx = fmaxf(mx, v);
        }
        float s = 0.0f;
        for (int j = 0; j < RDIM; ++j) {
            const float e = __expf(Srow[j] - mx);
            Srow[j] = e;
            s += e;
        }
        const float inv = 1.0f / s;
        for (int j = 0; j < RDIM; ++j) Srow[j] *= inv;
    }
    __syncthreads();

    float* pb = probs + ((size_t)h * CDIM + c) * (RDIM * RDIM);
#pragma unroll
    for (int it = 0; it < 16; ++it) {
        const int f4 = it * 256 + t;
        const int i  = f4 >> 5;
        const int j4 = (f4 & 31) << 2;
        *(float4*)(pb + (size_t)i * RDIM + j4) = *(const float4*)(&Ss[i * SP + j4]);
    }

    {
        float acc[8][4];
#pragma unroll
        for (int u = 0; u < 8; ++u)
#pragma unroll
            for (int q = 0; q < 4; ++q) acc[u][q] = 0.0f;

        for (int j = 0; j < RDIM; ++j) {
            const float4 v4 = *(const float4*)(&Vs[j * QP + (tx << 2)]);
#pragma unroll
            for (int u = 0; u < 8; ++u) {
                const float p = Ss[(ty + 16 * u) * SP + j];
                acc[u][0] = fmaf(p, v4.x, acc[u][0]);
                acc[u][1] = fmaf(p, v4.y, acc[u][1]);
                acc[u][2] = fmaf(p, v4.z, acc[u][2]);
                acc[u][3] = fmaf(p, v4.w, acc[u][3]);
            }
        }
        // ctx -> bf16 hi/lo directly (feeds out-projection HMMA GEMM)
#pragma unroll
        for (int u = 0; u < 8; ++u) {
            const int i = ty + 16 * u;
            const size_t ob = ((size_t)i * CDIM + c) * EDIM + h * DDIM + (tx << 2);
            __nv_bfloat16 h0, h1, h2, h3, l0, l1, l2, l3;
            split2(acc[u][0], h0, l0); split2(acc[u][1], h1, l1);
            split2(acc[u][2], h2, l2); split2(acc[u][3], h3, l3);
            *(__nv_bfloat162*)(g_ah + ob)     = __nv_bfloat162(h0, h1);
            *(__nv_bfloat162*)(g_ah + ob + 2) = __nv_bfloat162(h2, h3);
            *(__nv_bfloat162*)(g_al + ob)     = __nv_bfloat162(l0, l1);
            *(__nv_bfloat162*)(g_al + ob + 2) = __nv_bfloat162(l2, l3);
        }
    }
}

// ---------------------------------------------------------------------------
extern "C" void kernel_launch(void* const* d_in, const int* in_sizes, int n_in,
                              void* d_out, int out_size)
{
    const float* x  = (const float*)d_in[0];
    const unsigned char* mask = (const unsigned char*)d_in[2];
    const float* wq = (const float*)d_in[3];
    const float* bq = (const float*)d_in[4];
    const float* wk = (const float*)d_in[5];
    const float* bk = (const float*)d_in[6];
    const float* wv = (const float*)d_in[7];
    const float* bv = (const float*)d_in[8];
    const float* wo = (const float*)d_in[9];
    const float* bo = (const float*)d_in[10];

    float* out   = (float*)d_out;                    // (R, C, 1, E)
    float* probs = out + (size_t)MDIM * EDIM;        // (H, C, 1, R, R)

    const int gemm_smem = 2 * BUF_BYTES;             // 81920
    cudaFuncSetAttribute(gemm_tc, cudaFuncAttributeMaxDynamicSharedMemorySize, gemm_smem);
    const int attn_smem = (3 * 128 * QP + 128 * SP + 128) * (int)sizeof(float);
    cudaFuncSetAttribute(attn_kernel, cudaFuncAttributeMaxDynamicSharedMemorySize, attn_smem);

    conv_w<<<2304, 1024>>>(wq, wk, wv, wo, bq, bk, bv, bo);
    conv_x<<<9216, 1024>>>(x, MDIM * EDIM / 4);
    gemm_tc<<<dim3(MDIM / 128, 18), 512, gemm_smem>>>(0, 0, out);           // qkv
    attn_kernel<<<dim3(CDIM, HDIM), 256, attn_smem>>>(mask, probs);
    gemm_tc<<<dim3(MDIM / 128, 6), 512, gemm_smem>>>(3 * EDIM, 1, out);     // out proj
}

// round 4
// speedup vs baseline: 2.6306x; 1.1021x over previous
#include <cuda_runtime.h>
#include <cuda_bf16.h>
#include <cstdint>

#define RDIM 128
#define CDIM 384
#define EDIM 768
#define HDIM 12
#define DDIM 64
#define MDIM (RDIM * CDIM)   // 49152

// GEMM tiling
#define BK 64
#define PITCH 72                            // bf16/row (144B) — LDSM at 4-phase floor
#define MTX_BYTES (128 * PITCH * 2)         // 18432
#define BUF_BYTES (4 * MTX_BYTES)           // 73728 (Ah, Al, Bh, Bl)

// attention smem map (bytes)
#define PA 72      // 64-col bf16 tiles, 144B rows
#define PP 136     // 128-col bf16 P tiles, 272B rows
#define SP 132     // fp32 S pitch
#define AT_QH 0
#define AT_QL 18432
#define AT_KH 36864
#define AT_KL 55296
#define AT_PH 0          /* aliases Q/K after S is built */
#define AT_PL 34816
#define AT_VH 73728
#define AT_VL 92160
#define AT_VTH 110592
#define AT_VTL 128000
#define AT_S   145408    /* 128 x 132 fp32 = 67584 */
#define AT_MK  212992
#define AT_TOTAL 213504

// ---------------- device scratch (allocation-free rule) ----------------
__device__ __nv_bfloat16 g_ah[(size_t)MDIM * EDIM];     // A hi (x, then ctx)
__device__ __nv_bfloat16 g_al[(size_t)MDIM * EDIM];     // A lo
__device__ __nv_bfloat16 g_wh[(size_t)4 * EDIM * EDIM]; // packed wq|wk|wv|wo hi
__device__ __nv_bfloat16 g_wl[(size_t)4 * EDIM * EDIM]; // lo
__device__ float g_bias[4 * EDIM];
// q/k/v in attention tile layout [c][h][i][d], bf16 hi/lo
__device__ __nv_bfloat16 g_qh[(size_t)MDIM * EDIM];
__device__ __nv_bfloat16 g_ql[(size_t)MDIM * EDIM];
__device__ __nv_bfloat16 g_kh[(size_t)MDIM * EDIM];
__device__ __nv_bfloat16 g_kl[(size_t)MDIM * EDIM];
__device__ __nv_bfloat16 g_vh[(size_t)MDIM * EDIM];
__device__ __nv_bfloat16 g_vl[(size_t)MDIM * EDIM];

// ---------------- helpers ----------------
__device__ __forceinline__ uint32_t smem_to_u32(const void* p) {
    uint32_t a;
    asm("{ .reg .u64 t; cvta.to.shared.u64 t, %1; cvt.u32.u64 %0, t; }"
        : "=r"(a) : "l"(p));
    return a;
}
__device__ __forceinline__ void cp16(uint32_t dst, const void* src) {
    asm volatile("cp.async.cg.shared.global [%0], [%1], 16;"
                 :: "r"(dst), "l"(src) : "memory");
}
__device__ __forceinline__ void cp_commit() {
    asm volatile("cp.async.commit_group;" ::: "memory");
}
__device__ __forceinline__ void cp_wait0() {
    asm volatile("cp.async.wait_group 0;" ::: "memory");
}
__device__ __forceinline__ void ldmx4(uint32_t (&r)[4], uint32_t addr) {
    asm volatile("ldmatrix.sync.aligned.m8n8.x4.shared.b16 {%0,%1,%2,%3}, [%4];"
                 : "=r"(r[0]), "=r"(r[1]), "=r"(r[2]), "=r"(r[3]) : "r"(addr));
}
__device__ __forceinline__ void mma16816(float (&d)[4], const uint32_t (&a)[4],
                                         uint32_t b0, uint32_t b1) {
    asm volatile(
        "mma.sync.aligned.m16n8k16.row.col.f32.bf16.bf16.f32 "
        "{%0,%1,%2,%3}, {%4,%5,%6,%7}, {%8,%9}, {%0,%1,%2,%3};"
        : "+f"(d[0]), "+f"(d[1]), "+f"(d[2]), "+f"(d[3])
        : "r"(a[0]), "r"(a[1]), "r"(a[2]), "r"(a[3]), "r"(b0), "r"(b1));
}
__device__ __forceinline__ void split2(float f, __nv_bfloat16& h, __nv_bfloat16& l) {
    h = __float2bfloat16(f);
    l = __float2bfloat16(f - __bfloat162float(h));
}

// ---------------- conversion kernels ----------------
__global__ void conv_x(const float* __restrict__ src, int n4) {
    int i = blockIdx.x * blockDim.x + threadIdx.x;
    if (i >= n4) return;
    float4 v = ((const float4*)src)[i];
    __nv_bfloat16 h0, h1, h2, h3, l0, l1, l2, l3;
    split2(v.x, h0, l0); split2(v.y, h1, l1); split2(v.z, h2, l2); split2(v.w, h3, l3);
    size_t o = (size_t)i * 4;
    *(__nv_bfloat162*)(g_ah + o)     = __nv_bfloat162(h0, h1);
    *(__nv_bfloat162*)(g_ah + o + 2) = __nv_bfloat162(h2, h3);
    *(__nv_bfloat162*)(g_al + o)     = __nv_bfloat162(l0, l1);
    *(__nv_bfloat162*)(g_al + o + 2) = __nv_bfloat162(l2, l3);
}

__global__ void conv_w(const float* __restrict__ wq, const float* __restrict__ wk,
                       const float* __restrict__ wv, const float* __restrict__ wo,
                       const float* __restrict__ bq, const float* __restrict__ bk,
                       const float* __restrict__ bv, const float* __restrict__ bo)
{
    const size_t WSZ = (size_t)EDIM * EDIM;
    size_t i = (size_t)blockIdx.x * blockDim.x + threadIdx.x;
    int sel = (int)(i / WSZ);
    size_t off = i - (size_t)sel * WSZ;
    const float* w = (sel == 0) ? wq : (sel == 1) ? wk : (sel == 2) ? wv : wo;
    __nv_bfloat16 h, l;
    split2(w[off], h, l);
    g_wh[i] = h; g_wl[i] = l;
    if (i < 4 * EDIM) {
        int s = (int)(i / EDIM), r = (int)(i % EDIM);
        const float* b = (s == 0) ? bq : (s == 1) ? bk : (s == 2) ? bv : bo;
        g_bias[i] = b[r];
    }
}

// ---------------- split-bf16 HMMA GEMM (BK=64) ----------------
// C[128x128] tile = A[128,768] * Wpacked[nb..nb+128, 768]^T (+bias)
// mode 0: scatter q/k/v bf16 hi/lo ([c][h][i][d], q scaled); mode 1: out[m][f]
__global__ __launch_bounds__(512)
void gemm_tc(int n_off, int mode, float* __restrict__ outp)
{
    extern __shared__ char smdyn[];
    const uint32_t smb = smem_to_u32(smdyn);
    const int t = threadIdx.x;
    const int wid = t >> 5, lane = t & 31;
    const int wm = wid & 3, wn = wid >> 2;          // 4x4 warp grid
    const int bm = blockIdx.x * 128;
    const int nb = n_off + blockIdx.y * 128;

    const __nv_bfloat16* srcs[4] = {
        g_ah + (size_t)bm * EDIM, g_al + (size_t)bm * EDIM,
        g_wh + (size_t)nb * EDIM, g_wl + (size_t)nb * EDIM };

    float acc[2][4][4];
#pragma unroll
    for (int mi = 0; mi < 2; ++mi)
#pragma unroll
        for (int ni = 0; ni < 4; ++ni)
#pragma unroll
            for (int e = 0; e < 4; ++e) acc[mi][ni][e] = 0.0f;

    const int lrow8 = (lane & 7) + ((lane >> 3) & 1) * 8;
    const int lkoff = (lane >> 4) * 8;

    // prefetch chunk 0: per matrix 1024 chunks of 16B; 512 threads x 2
    {
#pragma unroll
        for (int kk = 0; kk < 2; ++kk) {
            const int id = t + kk * 512;
            const int r = id >> 3, cl = id & 7;
            const uint32_t d = smb + (uint32_t)(r * (PITCH * 2) + cl * 16);
            const int s = r * EDIM + cl * 8;
#pragma unroll
            for (int m = 0; m < 4; ++m)
                cp16(d + m * MTX_BYTES, srcs[m] + s);
        }
        cp_commit();
    }

    const int NC = EDIM / BK;  // 12
#pragma unroll 1
    for (int ch = 0; ch < NC; ++ch) {
        cp_wait0();
        __syncthreads();
        if (ch + 1 < NC) {
            const uint32_t bufn = ((ch + 1) & 1) * BUF_BYTES;
#pragma unroll
            for (int kk = 0; kk < 2; ++kk) {
                const int id = t + kk * 512;
                const int r = id >> 3, cl = id & 7;
                const uint32_t d = smb + bufn + (uint32_t)(r * (PITCH * 2) + cl * 16);
                const int s = r * EDIM + (ch + 1) * BK + cl * 8;
#pragma unroll
                for (int m = 0; m < 4; ++m)
                    cp16(d + m * MTX_BYTES, srcs[m] + s);
            }
            cp_commit();
        }
        const uint32_t buf = smb + (ch & 1) * BUF_BYTES;
        const uint32_t aAh = buf + (uint32_t)((wm * 32 + lrow8) * (PITCH * 2));
        const uint32_t aB  = buf + 2 * MTX_BYTES +
                             (uint32_t)((wn * 32 + lrow8) * (PITCH * 2));
#pragma unroll
        for (int ks = 0; ks < 4; ++ks) {
            const uint32_t kbyte = (uint32_t)((ks * 16 + lkoff) * 2);
            uint32_t ah[2][4], al[2][4], bh[2][4], bl[2][4];
#pragma unroll
            for (int mi = 0; mi < 2; ++mi) {
                ldmx4(ah[mi], aAh + (uint32_t)(mi * 16 * PITCH * 2) + kbyte);
                ldmx4(al[mi], aAh + MTX_BYTES + (uint32_t)(mi * 16 * PITCH * 2) + kbyte);
            }
#pragma unroll
            for (int nbk = 0; nbk < 2; ++nbk) {
                ldmx4(bh[nbk], aB + (uint32_t)(nbk * 16 * PITCH * 2) + kbyte);
                ldmx4(bl[nbk], aB + MTX_BYTES + (uint32_t)(nbk * 16 * PITCH * 2) + kbyte);
            }
#pragma unroll
            for (int mi = 0; mi < 2; ++mi)
#pragma unroll
                for (int ni = 0; ni < 4; ++ni) {
                    const int nk = ni >> 1, lo = ni & 1;
                    mma16816(acc[mi][ni], ah[mi], bh[nk][lo], bh[nk][lo + 2]);
                    mma16816(acc[mi][ni], ah[mi], bl[nk][lo], bl[nk][lo + 2]);
                    mma16816(acc[mi][ni], al[mi], bh[nk][lo], bh[nk][lo + 2]);
                }
        }
    }

    // epilogue
    const int r0 = bm + wm * 32 + (lane >> 2);
    const int cbase = nb + wn * 32 + (lane & 3) * 2;
#pragma unroll
    for (int mi = 0; mi < 2; ++mi) {
#pragma unroll
        for (int half = 0; half < 2; ++half) {
            const int m = r0 + mi * 16 + half * 8;
            const int i_ = m / CDIM, c_ = m % CDIM;
#pragma unroll
            for (int ni = 0; ni < 4; ++ni) {
                const int ng = cbase + ni * 8;
                float ox = acc[mi][ni][half * 2 + 0] + g_bias[ng + 0];
                float oy = acc[mi][ni][half * 2 + 1] + g_bias[ng + 1];
                if (mode == 0) {
                    if (ng < EDIM) { ox *= 0.125f; oy *= 0.125f; }
                    const int sel = ng / EDIM, f = ng % EDIM, h = f >> 6, d = f & 63;
                    __nv_bfloat16* dh = (sel == 0) ? g_qh : (sel == 1) ? g_kh : g_vh;
                    __nv_bfloat16* dl = (sel == 0) ? g_ql : (sel == 1) ? g_kl : g_vl;
                    const size_t off = (((size_t)c_ * HDIM + h) * RDIM + i_) * DDIM + d;
                    __nv_bfloat16 hx, lx, hy, ly;
                    split2(ox, hx, lx); split2(oy, hy, ly);
                    *(__nv_bfloat162*)(dh + off) = __nv_bfloat162(hx, hy);
                    *(__nv_bfloat162*)(dl + off) = __nv_bfloat162(lx, ly);
                } else {
                    float2 o; o.x = ox; o.y = oy;
                    *(float2*)(outp + (size_t)m * EDIM + (ng - 3 * EDIM)) = o;
                }
            }
        }
    }
}

// ---------------- HMMA attention per (c,h) ----------------
__global__ __launch_bounds__(256)
void attn_tc(const unsigned char* __restrict__ mask, float* __restrict__ probs)
{
    extern __shared__ char sm[];
    const uint32_t smb = smem_to_u32(sm);
    float* Ss = (float*)(sm + AT_S);
    float* Mk = (float*)(sm + AT_MK);

    const int c = blockIdx.x, h = blockIdx.y;
    const int t = threadIdx.x, wid = t >> 5, lane = t & 31;
    const size_t gbase = ((size_t)c * HDIM + h) * (RDIM * DDIM);

    // load 6 tiles (q/k/v hi+lo) via cp.async: each 1024 16B chunks
    {
        const __nv_bfloat16* srcs[6] = { g_qh + gbase, g_ql + gbase, g_kh + gbase,
                                         g_kl + gbase, g_vh + gbase, g_vl + gbase };
        const uint32_t dsts[6] = { smb + AT_QH, smb + AT_QL, smb + AT_KH,
                                   smb + AT_KL, smb + AT_VH, smb + AT_VL };
#pragma unroll
        for (int m = 0; m < 6; ++m)
#pragma unroll
            for (int k = 0; k < 4; ++k) {
                const int id = t + k * 256;
                const int r = id >> 3, cl = id & 7;
                cp16(dsts[m] + (uint32_t)(r * (PA * 2) + cl * 16),
                     srcs[m] + (size_t)r * DDIM + cl * 8);
            }
        cp_commit();
    }
    if (t < RDIM) Mk[t] = mask[(size_t)t * CDIM + c] ? 1.0f : 0.0f;
    cp_wait0();
    __syncthreads();

    // transpose V [j][d] -> Vt [d][j]
    {
        const __nv_bfloat16* vh = (const __nv_bfloat16*)(sm + AT_VH);
        const __nv_bfloat16* vl = (const __nv_bfloat16*)(sm + AT_VL);
        __nv_bfloat16* vth = (__nv_bfloat16*)(sm + AT_VTH);
        __nv_bfloat16* vtl = (__nv_bfloat16*)(sm + AT_VTL);
#pragma unroll
        for (int k = 0; k < 32; ++k) {
            const int idx = t + k * 256;
            const int j = idx >> 6, d = idx & 63;
            vth[d * PP + j] = vh[j * PA + d];
            vtl[d * PP + j] = vl[j * PA + d];
        }
    }

    const int wm = wid & 3, wn = wid >> 2;       // 4 x 2 warp grid
    const int lrow8 = (lane & 7) + ((lane >> 3) & 1) * 8;
    const int lkoff = (lane >> 4) * 8;

    // ---- S = Q K^T : warp tile 32(m) x 64(n), k=64 ----
    {
        float acc[2][8][4];
#pragma unroll
        for (int mi = 0; mi < 2; ++mi)
#pragma unroll
            for (int ni = 0; ni < 8; ++ni)
#pragma unroll
                for (int e = 0; e < 4; ++e) acc[mi][ni][e] = 0.0f;

        const uint32_t aQ = smb + AT_QH + (uint32_t)((wm * 32 + lrow8) * (PA * 2));
        const uint32_t aK = smb + AT_KH + (uint32_t)((wn * 64 + lrow8) * (PA * 2));
#pragma unroll
        for (int ks = 0; ks < 4; ++ks) {
            const uint32_t kb = (uint32_t)((ks * 16 + lkoff) * 2);
            uint32_t qh[2][4], ql[2][4], kh[4][4], kl[4][4];
#pragma unroll
            for (int mi = 0; mi < 2; ++mi) {
                ldmx4(qh[mi], aQ + (uint32_t)(mi * 16 * PA * 2) + kb);
                ldmx4(ql[mi], aQ + 18432u + (uint32_t)(mi * 16 * PA * 2) + kb);
            }
#pragma unroll
            for (int nbk = 0; nbk < 4; ++nbk) {
                ldmx4(kh[nbk], aK + (uint32_t)(nbk * 16 * PA * 2) + kb);
                ldmx4(kl[nbk], aK + 18432u + (uint32_t)(nbk * 16 * PA * 2) + kb);
            }
#pragma unroll
            for (int mi = 0; mi < 2; ++mi)
#pragma unroll
                for (int ni = 0; ni < 8; ++ni) {
                    const int nk = ni >> 1, lo = ni & 1;
                    mma16816(acc[mi][ni], qh[mi], kh[nk][lo], kh[nk][lo + 2]);
                    mma16816(acc[mi][ni], qh[mi], kl[nk][lo], kl[nk][lo + 2]);
                    mma16816(acc[mi][ni], ql[mi], kh[nk][lo], kh[nk][lo + 2]);
                }
        }
        // store S to smem fp32
#pragma unroll
        for (int mi = 0; mi < 2; ++mi)
#pragma unroll
            for (int ni = 0; ni < 8; ++ni) {
                const int r = wm * 32 + mi * 16 + (lane >> 2);
                const int col = wn * 64 + ni * 8 + (lane & 3) * 2;
                float2 lo2; lo2.x = acc[mi][ni][0]; lo2.y = acc[mi][ni][1];
                float2 hi2; hi2.x = acc[mi][ni][2]; hi2.y = acc[mi][ni][3];
                *(float2*)&Ss[r * SP + col] = lo2;
                *(float2*)&Ss[(r + 8) * SP + col] = hi2;
            }
    }
    __syncthreads();

    // ---- masked softmax, one row per thread ----
    if (t < RDIM) {
        float* Srow = Ss + t * SP;
        float mx = -3.0e38f;
        for (int j = 0; j < RDIM; ++j) {
            float v = Srow[j];
            if (Mk[j] != 0.0f) v = -10000.0f;
            Srow[j] = v;
            mx = fmaxf(mx, v);
        }
        float s = 0.0f;
        for (int j = 0; j < RDIM; ++j) {
            const float e = __expf(Srow[j] - mx);
            Srow[j] = e;
            s += e;
        }
        const float inv = 1.0f / s;
        for (int j = 0; j < RDIM; ++j) Srow[j] *= inv;
    }
    __syncthreads();

    // ---- write attn_probs + split P -> bf16 hi/lo (aliases Q/K smem) ----
    {
        float* pb = probs + ((size_t)h * CDIM + c) * (RDIM * RDIM);
#pragma unroll
        for (int it = 0; it < 16; ++it) {
            const int f4 = it * 256 + t;
            const int i = f4 >> 5;
            const int j4 = (f4 & 31) << 2;
            *(float4*)(pb + (size_t)i * RDIM + j4) = *(const float4*)&Ss[i * SP + j4];
        }
        __nv_bfloat16* ph = (__nv_bfloat16*)(sm + AT_PH);
        __nv_bfloat16* pl = (__nv_bfloat16*)(sm + AT_PL);
#pragma unroll
        for (int k = 0; k < 64; ++k) {
            const int idx = t + k * 256;
            const int i = idx >> 7, j = idx & 127;
            __nv_bfloat16 hh, ll;
            split2(Ss[i * SP + j], hh, ll);
            ph[i * PP + j] = hh;
            pl[i * PP + j] = ll;
        }
    }
    __syncthreads();

    // ---- ctx = P V : warp tile 32(m) x 32(n), k=128 ----
    {
        float acc[2][4][4];
#pragma unroll
        for (int mi = 0; mi < 2; ++mi)
#pragma unroll
            for (int ni = 0; ni < 4; ++ni)
#pragma unroll
                for (int e = 0; e < 4; ++e) acc[mi][ni][e] = 0.0f;

        const uint32_t aP = smb + AT_PH + (uint32_t)((wm * 32 + lrow8) * (PP * 2));
        const uint32_t aV = smb + AT_VTH + (uint32_t)((wn * 32 + lrow8) * (PP * 2));
#pragma unroll
        for (int ks = 0; ks < 8; ++ks) {
            const uint32_t kb = (uint32_t)((ks * 16 + lkoff) * 2);
            uint32_t ph[2][4], pl[2][4], vh[2][4], vl[2][4];
#pragma unroll
            for (int mi = 0; mi < 2; ++mi) {
                ldmx4(ph[mi], aP + (uint32_t)(mi * 16 * PP * 2) + kb);
                ldmx4(pl[mi], aP + 34816u + (uint32_t)(mi * 16 * PP * 2) + kb);
            }
#pragma unroll
            for (int nbk = 0; nbk < 2; ++nbk) {
                ldmx4(vh[nbk], aV + (uint32_t)(nbk * 16 * PP * 2) + kb);
                ldmx4(vl[nbk], aV + 17408u + (uint32_t)(nbk * 16 * PP * 2) + kb);
            }
#pragma unroll
            for (int mi = 0; mi < 2; ++mi)
#pragma unroll
                for (int ni = 0; ni < 4; ++ni) {
                    const int nk = ni >> 1, lo = ni & 1;
                    mma16816(acc[mi][ni], ph[mi], vh[nk][lo], vh[nk][lo + 2]);
                    mma16816(acc[mi][ni], ph[mi], vl[nk][lo], vl[nk][lo + 2]);
                    mma16816(acc[mi][ni], pl[mi], vh[nk][lo], vh[nk][lo + 2]);
                }
        }
        // ctx epilogue -> g_ah/g_al (feeds out-projection)
#pragma unroll
        for (int mi = 0; mi < 2; ++mi)
#pragma unroll
            for (int half = 0; half < 2; ++half) {
                const int i = wm * 32 + mi * 16 + (lane >> 2) + half * 8;
#pragma unroll
                for (int ni = 0; ni < 4; ++ni) {
                    const int d = wn * 32 + ni * 8 + (lane & 3) * 2;
                    const size_t ob = ((size_t)i * CDIM + c) * EDIM + h * DDIM + d;
                    __nv_bfloat16 hx, lx, hy, ly;
                    split2(acc[mi][ni][half * 2 + 0], hx, lx);
                    split2(acc[mi][ni][half * 2 + 1], hy, ly);
                    *(__nv_bfloat162*)(g_ah + ob) = __nv_bfloat162(hx, hy);
                    *(__nv_bfloat162*)(g_al + ob) = __nv_bfloat162(lx, ly);
                }
            }
    }
}

// ---------------------------------------------------------------------------
extern "C" void kernel_launch(void* const* d_in, const int* in_sizes, int n_in,
                              void* d_out, int out_size)
{
    const float* x  = (const float*)d_in[0];
    const unsigned char* mask = (const unsigned char*)d_in[2];
    const float* wq = (const float*)d_in[3];
    const float* bq = (const float*)d_in[4];
    const float* wk = (const float*)d_in[5];
    const float* bk = (const float*)d_in[6];
    const float* wv = (const float*)d_in[7];
    const float* bv = (const float*)d_in[8];
    const float* wo = (const float*)d_in[9];
    const float* bo = (const float*)d_in[10];

    float* out   = (float*)d_out;                    // (R, C, 1, E)
    float* probs = out + (size_t)MDIM * EDIM;        // (H, C, 1, R, R)

    const int gemm_smem = 2 * BUF_BYTES;             // 147456
    cudaFuncSetAttribute(gemm_tc, cudaFuncAttributeMaxDynamicSharedMemorySize, gemm_smem);
    cudaFuncSetAttribute(attn_tc, cudaFuncAttributeMaxDynamicSharedMemorySize, AT_TOTAL);

    conv_w<<<2304, 1024>>>(wq, wk, wv, wo, bq, bk, bv, bo);
    conv_x<<<9216, 1024>>>(x, MDIM * EDIM / 4);
    gemm_tc<<<dim3(MDIM / 128, 18), 512, gemm_smem>>>(0, 0, out);           // qkv
    attn_tc<<<dim3(CDIM, HDIM), 256, AT_TOTAL>>>(mask, probs);
    gemm_tc<<<dim3(MDIM / 128, 6), 512, gemm_smem>>>(3 * EDIM, 1, out);     // out proj
}